// round 15
// baseline (speedup 1.0000x reference)
#include <cuda_runtime.h>
#include <cstdint>

#define B_ 16
#define D_ 16
#define H_ 288
#define W_ 512
#define N_ (H_*W_)   // 147456
#define L_ 17
#define K1CH 18      // k1 chunks -> 8192 px/block; 288 blocks = ONE wave @2/SM
#define K3CH 24      // k3 chunks -> 6144 px/block; 384 blocks = ONE wave @3/SM

// persistent scratch (re-zeroed every launch: graph replays reuse it)
__device__ float g_sums[B_][L_][D_];
__device__ float g_cnt[B_][L_];
__device__ float g_means[B_][L_][D_];
__device__ float g_w[B_][L_];

__device__ __forceinline__ uint32_t smem_u32(const void* p) {
    uint32_t a;
    asm("{ .reg .u64 t; cvta.to.shared.u64 t, %1; cvt.u32.u64 %0, t; }"
        : "=r"(a) : "l"(p));
    return a;
}

// ---------------------------------------------------------------- kernel 0
__global__ void k0_zero(float* out) {
    int t = blockIdx.x * blockDim.x + threadIdx.x;
    int stride = gridDim.x * blockDim.x;
    if (t == 0) out[0] = 0.f;
    float* s = &g_sums[0][0][0];
    for (int i = t; i < B_*L_*D_; i += stride) s[i] = 0.f;
    float* c = &g_cnt[0][0];
    for (int i = t; i < B_*L_; i += stride) c[i] = 0.f;
}

// ---------------------------------------------------------------- kernel 1
// Per-label sums + counts. Distributed cp.async (LDGSTS) per-warp pipeline:
// every thread streams its own 16B emb chunks into a 3-stage SMEM ring via
// the async engine (zero data registers, no block syncs: warp w stages ONLY
// its dims 2w,2w+1 and consumes only those; seg is register-prefetched LDG).
// wait_group 1 keeps 2 stages (8x16B/thread) continuously in flight.
// Scatter into per-thread indexed smem accumulators (R9 structure).
// Dynamic smem 84KB -> 2 blocks/SM; 288 blocks = one wave.
__global__ void __launch_bounds__(256, 2) k1_sums(const float* __restrict__ emb,
                                                  const int* __restrict__ seg) {
    extern __shared__ float smf[];
    // layout: stage ring sd[3][8][2][256] floats (12288), then ac0, ac1
    float* __restrict__ sd  = smf;                       // 49152 B
    float* __restrict__ ac0 = smf + 12288;               // 8*32*17 floats
    float* __restrict__ ac1 = ac0 + 8 * 32 * 17;

    const int b    = blockIdx.y;
    const int lane = threadIdx.x;
    const int w    = threadIdx.y;
    const int chunk = N_ / K1CH;                   // 8192
    const int lo    = blockIdx.x * chunk;
    const int ITERS = chunk / 256;                 // 32 (256 px per warp-iter)

    float* __restrict__ a0 = ac0 + (w * 32 + lane) * 17;   // thread-private
    float* __restrict__ a1 = ac1 + (w * 32 + lane) * 17;
#pragma unroll
    for (int i = 0; i < 17; i++) { a0[i] = 0.f; a1[i] = 0.f; }

    const float* __restrict__ e0 = emb + ((size_t)b * D_ + 2 * w) * N_;
    const float* __restrict__ e1 = e0 + N_;
    const int*   __restrict__ sp = seg + (size_t)b * N_;

    // per-thread smem addresses: sd[buf][w][d][grp*128 + lane*4]
    // float offset(buf,d,grp) = buf*4096 + w*512 + d*256 + grp*128 + lane*4
    const uint32_t sd0 = smem_u32(sd + w * 512 + lane * 4);
#define SD_DST(BUF, DD, GRP) (sd0 + (uint32_t)(((BUF)*4096 + (DD)*256 + (GRP)*128) * 4))

#define CPA16(DST, SRC)                                                        \
    asm volatile("cp.async.cg.shared.global [%0], [%1], 16;"                   \
                 :: "r"(DST), "l"((const void*)(SRC)) : "memory")

#define ISSUE(J)                                                               \
    {                                                                          \
        int _j = (J);                                                          \
        int _buf = _j % 3;                                                     \
        int _n = lo + _j * 256 + lane * 4;                                     \
        CPA16(SD_DST(_buf, 0, 0), e0 + _n);                                    \
        CPA16(SD_DST(_buf, 0, 1), e0 + _n + 128);                              \
        CPA16(SD_DST(_buf, 1, 0), e1 + _n);                                    \
        CPA16(SD_DST(_buf, 1, 1), e1 + _n + 128);                              \
        asm volatile("cp.async.commit_group;" ::: "memory");                   \
    }

    ISSUE(0); ISSUE(1);

    int cnt[16];
#pragma unroll
    for (int l = 0; l < 16; l++) cnt[l] = 0;

    // seg depth-1 register prefetch
    int n0 = lo + lane * 4;
    int4 sAx = *(const int4*)(sp + n0);
    int4 sAy = *(const int4*)(sp + n0 + 128);

    for (int it = 0; it < ITERS; ++it) {
        // prefetch next stage's seg
        int nn = (it + 1 < ITERS) ? (lo + (it + 1) * 256 + lane * 4) : n0;
        int4 sBx = *(const int4*)(sp + nn);
        int4 sBy = *(const int4*)(sp + nn + 128);

        // stage it must be complete
        if (it == ITERS - 1) {
            asm volatile("cp.async.wait_group 0;" ::: "memory");
        } else {
            asm volatile("cp.async.wait_group 1;" ::: "memory");
        }

        const int buf = it % 3;
        const float* st = sd + buf * 4096 + w * 512;
        float4 v00 = *(const float4*)(st + lane * 4);            // dim0 grp0
        float4 v01 = *(const float4*)(st + 128 + lane * 4);      // dim0 grp1
        float4 v10 = *(const float4*)(st + 256 + lane * 4);      // dim1 grp0
        float4 v11 = *(const float4*)(st + 384 + lane * 4);      // dim1 grp1

        // two independent indexed-accumulate chains (dim0 / dim1)
        a0[sAx.x] += v00.x;  a1[sAx.x] += v10.x;
        a0[sAx.y] += v00.y;  a1[sAx.y] += v10.y;
        a0[sAx.z] += v00.z;  a1[sAx.z] += v10.z;
        a0[sAx.w] += v00.w;  a1[sAx.w] += v10.w;
        a0[sAy.x] += v01.x;  a1[sAy.x] += v11.x;
        a0[sAy.y] += v01.y;  a1[sAy.y] += v11.y;
        a0[sAy.z] += v01.z;  a1[sAy.z] += v11.z;
        a0[sAy.w] += v01.w;  a1[sAy.w] += v11.w;

        // rotating count warp: every iteration counted exactly once
        if (((it - w) & 7) == 0) {
#pragma unroll
            for (int l = 1; l <= 16; l++)
                cnt[l-1] += (sAx.x == l) + (sAx.y == l) + (sAx.z == l) + (sAx.w == l)
                          + (sAy.x == l) + (sAy.y == l) + (sAy.z == l) + (sAy.w == l);
        }

        // refill ring (buffer it%3 fully consumed above; per-warp private)
        if (it + 2 < ITERS) ISSUE(it + 2);

        sAx = sBx; sAy = sBy;
    }
#undef ISSUE
#undef CPA16
#undef SD_DST

    // reduce each thread's private sums across the warp, commit via atomics
#pragma unroll
    for (int s = 1; s < L_; s++) {
        float v0 = a0[s];
        float v1 = a1[s];
#pragma unroll
        for (int off = 16; off >= 1; off >>= 1) {
            v0 += __shfl_xor_sync(0xffffffffu, v0, off);
            v1 += __shfl_xor_sync(0xffffffffu, v1, off);
        }
        if (lane == 0) {
            atomicAdd(&g_sums[b][s][2 * w],     v0);
            atomicAdd(&g_sums[b][s][2 * w + 1], v1);
        }
    }
#pragma unroll
    for (int l = 0; l < 16; l++) {
        int c = cnt[l];
#pragma unroll
        for (int off = 16; off >= 1; off >>= 1)
            c += __shfl_xor_sync(0xffffffffu, c, off);
        if (lane == 0 && c > 0) atomicAdd(&g_cnt[b][l+1], (float)c);
    }
}

// ---------------------------------------------------------------- kernel 2
// Finalize means/weights + pairwise push (distance) term. Single block.
__global__ void k2_mid(float* out) {
    __shared__ int   pres[B_][L_];
    __shared__ float nlsh[B_];
    __shared__ float red[512];
    const int tid = threadIdx.x;

    for (int idx = tid; idx < B_*L_; idx += 512) {
        int b = idx / L_, l = idx % L_;
        pres[b][l] = (l != 0 && g_cnt[b][l] > 0.f) ? 1 : 0;
    }
    __syncthreads();
    if (tid < B_) {
        int nl = 0;
        for (int l = 0; l < L_; l++) nl += pres[tid][l];
        nlsh[tid] = (float)nl;
    }
    __syncthreads();

    for (int idx = tid; idx < B_*L_*D_; idx += 512) {
        int b = idx / (L_*D_);
        int l = (idx / D_) % L_;
        int d = idx % D_;
        float c = fmaxf(g_cnt[b][l], 1.f);
        g_means[b][l][d] = g_sums[b][l][d] / c;
    }
    for (int idx = tid; idx < B_*L_; idx += 512) {
        int b = idx / L_, l = idx % L_;
        float c  = fmaxf(g_cnt[b][l], 1.f);
        float nl = fmaxf(nlsh[b], 1.f);
        g_w[b][l] = pres[b][l] ? (1.f / (c * nl * (float)B_)) : 0.f;
    }
    __syncthreads();   // g_means visible block-wide

    float acc = 0.f;
    for (int idx = tid; idx < B_*L_*L_; idx += 512) {
        int b = idx / (L_*L_);
        int i = (idx / L_) % L_;
        int j = idx % L_;
        if (i != j && pres[b][i] && pres[b][j]) {
            float nl = nlsh[b];
            if (nl > 1.f) {
                float ss = 0.f;
#pragma unroll
                for (int d = 0; d < D_; d++) {
                    float dm = g_means[b][i][d] - g_means[b][j][d];
                    ss = fmaf(dm, dm, ss);
                }
                float dist = sqrtf(ss);
                float p = fmaxf(1.5f - dist, 0.f);
                float denom = fmaxf(nl * (nl - 1.f), 1.f);
                acc += (p * p) / denom * 0.5f / (float)B_;
            }
        }
    }
    red[tid] = acc;
    __syncthreads();
    for (int s = 256; s > 0; s >>= 1) {
        if (tid < s) red[tid] += red[tid + s];
        __syncthreads();
    }
    if (tid == 0) atomicAdd(out, red[0]);
}

// ---------------------------------------------------------------- kernel 3
// Variance (pull) term, pre-weighted so it sums directly into the loss.
// 256 threads, 6 iters of 4 px, grid (24,16)=384 -> ONE wave @3/SM.
// Two 8-dim phases per 4-px group keep live float4s (and regs ~72) low.
__global__ void __launch_bounds__(256, 3) k3_var(const float* __restrict__ emb,
                                                 const int* __restrict__ seg,
                                                 float* out) {
    const int b = blockIdx.y;
    __shared__ float sm_m[D_][L_];   // [d][l]: 17-float stride, conflict-free
    __shared__ float sm_w[L_];
    __shared__ float wsum[8];
    const int tid = threadIdx.x;

    for (int idx = tid; idx < D_*L_; idx += 256) {
        int d = idx / L_, l = idx % L_;
        sm_m[d][l] = g_means[b][l][d];
    }
    if (tid < L_) sm_w[tid] = g_w[b][tid];
    if (tid < 8) wsum[tid] = 0.f;
    __syncthreads();

    const int chunk = N_ / K3CH;     // 6144 = 6 * 256 * 4
    const int lo    = blockIdx.x * chunk;
    const float* __restrict__ e  = emb + (size_t)b * D_ * N_;
    const int* __restrict__   sp = seg + (size_t)b * N_;

    float acc = 0.f;
#pragma unroll
    for (int itr = 0; itr < 6; itr++) {
        int n = lo + itr * (256 * 4) + tid * 4;
        int4 s4 = *(const int4*)(sp + n);
        float ssx = 0.f, ssy = 0.f, ssz = 0.f, ssw = 0.f;

#pragma unroll
        for (int ph = 0; ph < 2; ph++) {
            float4 v[8];
#pragma unroll
            for (int d = 0; d < 8; d++)
                v[d] = *(const float4*)(e + (size_t)(ph * 8 + d) * N_ + n);
#pragma unroll
            for (int d = 0; d < 8; d++) {
                const float* mrow = &sm_m[ph * 8 + d][0];
                float dx = v[d].x - mrow[s4.x]; ssx = fmaf(dx, dx, ssx);
                float dy = v[d].y - mrow[s4.y]; ssy = fmaf(dy, dy, ssy);
                float dz = v[d].z - mrow[s4.z]; ssz = fmaf(dz, dz, ssz);
                float dw = v[d].w - mrow[s4.w]; ssw = fmaf(dw, dw, ssw);
            }
        }

#define FIN(SS, S)                                                             \
        {                                                                      \
            float nrm = sqrtf(fmaxf((SS), 1e-12f));                            \
            float t = fmaxf(nrm - 0.5f, 0.f);                                  \
            acc = fmaf(sm_w[S], t * t, acc);                                   \
        }
        FIN(ssx, s4.x); FIN(ssy, s4.y); FIN(ssz, s4.z); FIN(ssw, s4.w);
#undef FIN
    }
#pragma unroll
    for (int off = 16; off >= 1; off >>= 1)
        acc += __shfl_xor_sync(0xffffffffu, acc, off);
    if ((tid & 31) == 0) wsum[tid >> 5] = acc;
    __syncthreads();
    if (tid < 8) {
        float a = wsum[tid];
#pragma unroll
        for (int off = 4; off >= 1; off >>= 1)
            a += __shfl_xor_sync(0xffu, a, off);
        if (tid == 0) atomicAdd(out, a);
    }
}

// ---------------------------------------------------------------- launch
extern "C" void kernel_launch(void* const* d_in, const int* in_sizes, int n_in,
                              void* d_out, int out_size) {
    const float* emb = (const float*)d_in[0];
    const int*   seg = (const int*)d_in[1];
    float*       out = (float*)d_out;

    const int K1_SMEM = (12288 + 2 * 8 * 32 * 17) * 4;   // 83968 B
    static int attr_done = 0;
    if (!attr_done) {
        cudaFuncSetAttribute(k1_sums, cudaFuncAttributeMaxDynamicSharedMemorySize,
                             K1_SMEM);
        attr_done = 1;
    }

    k0_zero<<<8, 256>>>(out);

    dim3 g1(K1CH, B_), b1(32, 8);
    k1_sums<<<g1, b1, K1_SMEM>>>(emb, seg);

    k2_mid<<<1, 512>>>(out);

    dim3 g3(K3CH, B_);
    k3_var<<<g3, 256>>>(emb, seg, out);
}

// round 16
// speedup vs baseline: 1.2170x; 1.2170x over previous
#include <cuda_runtime.h>
#include <cstdint>

#define B_ 16
#define D_ 16
#define H_ 288
#define W_ 512
#define N_ (H_*W_)   // 147456
#define L_ 17
#define K1CH 18      // k1 chunks -> 8192 px/block; 288 blocks = ONE wave @2/SM
#define K3CH 24      // k3 chunks -> 6144 px/block; 384 blocks = ONE wave @3/SM

// persistent scratch (re-zeroed every launch: graph replays reuse it)
__device__ float g_sums[B_][L_][D_];
__device__ float g_cnt[B_][L_];
__device__ float g_means[B_][L_][D_];
__device__ float g_w[B_][L_];

__device__ __forceinline__ uint32_t smem_u32(const void* p) {
    uint32_t a;
    asm("{ .reg .u64 t; cvta.to.shared.u64 t, %1; cvt.u32.u64 %0, t; }"
        : "=r"(a) : "l"(p));
    return a;
}

// ---------------------------------------------------------------- kernel 0
__global__ void k0_zero(float* out) {
    int t = blockIdx.x * blockDim.x + threadIdx.x;
    int stride = gridDim.x * blockDim.x;
    if (t == 0) out[0] = 0.f;
    float* s = &g_sums[0][0][0];
    for (int i = t; i < B_*L_*D_; i += stride) s[i] = 0.f;
    float* c = &g_cnt[0][0];
    for (int i = t; i < B_*L_; i += stride) c[i] = 0.f;
}

// ---------------------------------------------------------------- kernel 1
// Per-label sums + counts. cp.async per-warp 3-stage ring (R15) feeding
// FLOAT2-PACKED accumulators ac[w][s][lane]:
//  - one LDS.64+2FADD+STS.64 per pixel (8 RMW ops/warp-iter, was 32)
//  - lane-major layout -> lane l always banks (2l,2l+1): fixed degree-2,
//    label-independent -> crossbar ~18us < DRAM floor.
__global__ void __launch_bounds__(256, 2) k1_sums(const float* __restrict__ emb,
                                                  const int* __restrict__ seg) {
    extern __shared__ float smf[];
    // layout: stage ring sd[3][8][2][256] floats (12288), then float2 acc
    float*  __restrict__ sd = smf;                        // 49152 B
    float2* __restrict__ ac = (float2*)(smf + 12288);     // [8][17][32] f2

    const int b    = blockIdx.y;
    const int lane = threadIdx.x;
    const int w    = threadIdx.y;
    const int chunk = N_ / K1CH;                   // 8192
    const int lo    = blockIdx.x * chunk;
    const int ITERS = chunk / 256;                 // 32 (256 px per warp-iter)

    float2* __restrict__ ap = ac + (w * 17) * 32 + lane;   // thread-private
#pragma unroll
    for (int s = 0; s < L_; s++) ap[s * 32] = make_float2(0.f, 0.f);

    const float* __restrict__ e0 = emb + ((size_t)b * D_ + 2 * w) * N_;
    const float* __restrict__ e1 = e0 + N_;
    const int*   __restrict__ sp = seg + (size_t)b * N_;

    // per-thread smem addresses: sd[buf][w][d][grp*128 + lane*4]
    const uint32_t sd0 = smem_u32(sd + w * 512 + lane * 4);
#define SD_DST(BUF, DD, GRP) (sd0 + (uint32_t)(((BUF)*4096 + (DD)*256 + (GRP)*128) * 4))

#define CPA16(DST, SRC)                                                        \
    asm volatile("cp.async.cg.shared.global [%0], [%1], 16;"                   \
                 :: "r"(DST), "l"((const void*)(SRC)) : "memory")

#define ISSUE(J)                                                               \
    {                                                                          \
        int _j = (J);                                                          \
        int _buf = _j % 3;                                                     \
        int _n = lo + _j * 256 + lane * 4;                                     \
        CPA16(SD_DST(_buf, 0, 0), e0 + _n);                                    \
        CPA16(SD_DST(_buf, 0, 1), e0 + _n + 128);                              \
        CPA16(SD_DST(_buf, 1, 0), e1 + _n);                                    \
        CPA16(SD_DST(_buf, 1, 1), e1 + _n + 128);                              \
        asm volatile("cp.async.commit_group;" ::: "memory");                   \
    }

    ISSUE(0); ISSUE(1);

    int cnt[16];
#pragma unroll
    for (int l = 0; l < 16; l++) cnt[l] = 0;

    // seg depth-1 register prefetch
    int n0 = lo + lane * 4;
    int4 sAx = *(const int4*)(sp + n0);
    int4 sAy = *(const int4*)(sp + n0 + 128);

    for (int it = 0; it < ITERS; ++it) {
        // prefetch next stage's seg
        int nn = (it + 1 < ITERS) ? (lo + (it + 1) * 256 + lane * 4) : n0;
        int4 sBx = *(const int4*)(sp + nn);
        int4 sBy = *(const int4*)(sp + nn + 128);

        // stage it must be complete
        if (it == ITERS - 1) {
            asm volatile("cp.async.wait_group 0;" ::: "memory");
        } else {
            asm volatile("cp.async.wait_group 1;" ::: "memory");
        }

        const int buf = it % 3;
        const float* st = sd + buf * 4096 + w * 512;
        float4 v00 = *(const float4*)(st + lane * 4);            // dim0 grp0
        float4 v01 = *(const float4*)(st + 128 + lane * 4);      // dim0 grp1
        float4 v10 = *(const float4*)(st + 256 + lane * 4);      // dim1 grp0
        float4 v11 = *(const float4*)(st + 384 + lane * 4);      // dim1 grp1

        // float2-packed indexed accumulate: 1 LDS.64 + 2 FADD + 1 STS.64/px
        { float2 t = ap[sAx.x * 32]; t.x += v00.x; t.y += v10.x; ap[sAx.x * 32] = t; }
        { float2 t = ap[sAx.y * 32]; t.x += v00.y; t.y += v10.y; ap[sAx.y * 32] = t; }
        { float2 t = ap[sAx.z * 32]; t.x += v00.z; t.y += v10.z; ap[sAx.z * 32] = t; }
        { float2 t = ap[sAx.w * 32]; t.x += v00.w; t.y += v10.w; ap[sAx.w * 32] = t; }
        { float2 t = ap[sAy.x * 32]; t.x += v01.x; t.y += v11.x; ap[sAy.x * 32] = t; }
        { float2 t = ap[sAy.y * 32]; t.x += v01.y; t.y += v11.y; ap[sAy.y * 32] = t; }
        { float2 t = ap[sAy.z * 32]; t.x += v01.z; t.y += v11.z; ap[sAy.z * 32] = t; }
        { float2 t = ap[sAy.w * 32]; t.x += v01.w; t.y += v11.w; ap[sAy.w * 32] = t; }

        // rotating count warp: every iteration counted exactly once
        if (((it - w) & 7) == 0) {
#pragma unroll
            for (int l = 1; l <= 16; l++)
                cnt[l-1] += (sAx.x == l) + (sAx.y == l) + (sAx.z == l) + (sAx.w == l)
                          + (sAy.x == l) + (sAy.y == l) + (sAy.z == l) + (sAy.w == l);
        }

        // refill ring (buffer it%3 fully consumed above; per-warp private)
        if (it + 2 < ITERS) ISSUE(it + 2);

        sAx = sBx; sAy = sBy;
    }
#undef ISSUE
#undef CPA16
#undef SD_DST

    // reduce each thread's private sums across the warp, commit via atomics
#pragma unroll
    for (int s = 1; s < L_; s++) {
        float2 t = ap[s * 32];
        float v0 = t.x;
        float v1 = t.y;
#pragma unroll
        for (int off = 16; off >= 1; off >>= 1) {
            v0 += __shfl_xor_sync(0xffffffffu, v0, off);
            v1 += __shfl_xor_sync(0xffffffffu, v1, off);
        }
        if (lane == 0) {
            atomicAdd(&g_sums[b][s][2 * w],     v0);
            atomicAdd(&g_sums[b][s][2 * w + 1], v1);
        }
    }
#pragma unroll
    for (int l = 0; l < 16; l++) {
        int c = cnt[l];
#pragma unroll
        for (int off = 16; off >= 1; off >>= 1)
            c += __shfl_xor_sync(0xffffffffu, c, off);
        if (lane == 0 && c > 0) atomicAdd(&g_cnt[b][l+1], (float)c);
    }
}

// ---------------------------------------------------------------- kernel 2
// Finalize means/weights + pairwise push (distance) term. Single block.
__global__ void k2_mid(float* out) {
    __shared__ int   pres[B_][L_];
    __shared__ float nlsh[B_];
    __shared__ float red[512];
    const int tid = threadIdx.x;

    for (int idx = tid; idx < B_*L_; idx += 512) {
        int b = idx / L_, l = idx % L_;
        pres[b][l] = (l != 0 && g_cnt[b][l] > 0.f) ? 1 : 0;
    }
    __syncthreads();
    if (tid < B_) {
        int nl = 0;
        for (int l = 0; l < L_; l++) nl += pres[tid][l];
        nlsh[tid] = (float)nl;
    }
    __syncthreads();

    for (int idx = tid; idx < B_*L_*D_; idx += 512) {
        int b = idx / (L_*D_);
        int l = (idx / D_) % L_;
        int d = idx % D_;
        float c = fmaxf(g_cnt[b][l], 1.f);
        g_means[b][l][d] = g_sums[b][l][d] / c;
    }
    for (int idx = tid; idx < B_*L_; idx += 512) {
        int b = idx / L_, l = idx % L_;
        float c  = fmaxf(g_cnt[b][l], 1.f);
        float nl = fmaxf(nlsh[b], 1.f);
        g_w[b][l] = pres[b][l] ? (1.f / (c * nl * (float)B_)) : 0.f;
    }
    __syncthreads();   // g_means visible block-wide

    float acc = 0.f;
    for (int idx = tid; idx < B_*L_*L_; idx += 512) {
        int b = idx / (L_*L_);
        int i = (idx / L_) % L_;
        int j = idx % L_;
        if (i != j && pres[b][i] && pres[b][j]) {
            float nl = nlsh[b];
            if (nl > 1.f) {
                float ss = 0.f;
#pragma unroll
                for (int d = 0; d < D_; d++) {
                    float dm = g_means[b][i][d] - g_means[b][j][d];
                    ss = fmaf(dm, dm, ss);
                }
                float dist = sqrtf(ss);
                float p = fmaxf(1.5f - dist, 0.f);
                float denom = fmaxf(nl * (nl - 1.f), 1.f);
                acc += (p * p) / denom * 0.5f / (float)B_;
            }
        }
    }
    red[tid] = acc;
    __syncthreads();
    for (int s = 256; s > 0; s >>= 1) {
        if (tid < s) red[tid] += red[tid + s];
        __syncthreads();
    }
    if (tid == 0) atomicAdd(out, red[0]);
}

// ---------------------------------------------------------------- kernel 3
// Variance (pull) term, pre-weighted so it sums directly into the loss.
// 256 threads, 6 iters of 4 px, grid (24,16)=384 -> ONE wave @3/SM.
__global__ void __launch_bounds__(256, 3) k3_var(const float* __restrict__ emb,
                                                 const int* __restrict__ seg,
                                                 float* out) {
    const int b = blockIdx.y;
    __shared__ float sm_m[D_][L_];   // [d][l]: 17-float stride, conflict-free
    __shared__ float sm_w[L_];
    __shared__ float wsum[8];
    const int tid = threadIdx.x;

    for (int idx = tid; idx < D_*L_; idx += 256) {
        int d = idx / L_, l = idx % L_;
        sm_m[d][l] = g_means[b][l][d];
    }
    if (tid < L_) sm_w[tid] = g_w[b][tid];
    if (tid < 8) wsum[tid] = 0.f;
    __syncthreads();

    const int chunk = N_ / K3CH;     // 6144 = 6 * 256 * 4
    const int lo    = blockIdx.x * chunk;
    const float* __restrict__ e  = emb + (size_t)b * D_ * N_;
    const int* __restrict__   sp = seg + (size_t)b * N_;

    float acc = 0.f;
#pragma unroll
    for (int itr = 0; itr < 6; itr++) {
        int n = lo + itr * (256 * 4) + tid * 4;
        int4 s4 = *(const int4*)(sp + n);
        float ssx = 0.f, ssy = 0.f, ssz = 0.f, ssw = 0.f;

#pragma unroll
        for (int ph = 0; ph < 2; ph++) {
            float4 v[8];
#pragma unroll
            for (int d = 0; d < 8; d++)
                v[d] = *(const float4*)(e + (size_t)(ph * 8 + d) * N_ + n);
#pragma unroll
            for (int d = 0; d < 8; d++) {
                const float* mrow = &sm_m[ph * 8 + d][0];
                float dx = v[d].x - mrow[s4.x]; ssx = fmaf(dx, dx, ssx);
                float dy = v[d].y - mrow[s4.y]; ssy = fmaf(dy, dy, ssy);
                float dz = v[d].z - mrow[s4.z]; ssz = fmaf(dz, dz, ssz);
                float dw = v[d].w - mrow[s4.w]; ssw = fmaf(dw, dw, ssw);
            }
        }

#define FIN(SS, S)                                                             \
        {                                                                      \
            float nrm = sqrtf(fmaxf((SS), 1e-12f));                            \
            float t = fmaxf(nrm - 0.5f, 0.f);                                  \
            acc = fmaf(sm_w[S], t * t, acc);                                   \
        }
        FIN(ssx, s4.x); FIN(ssy, s4.y); FIN(ssz, s4.z); FIN(ssw, s4.w);
#undef FIN
    }
#pragma unroll
    for (int off = 16; off >= 1; off >>= 1)
        acc += __shfl_xor_sync(0xffffffffu, acc, off);
    if ((tid & 31) == 0) wsum[tid >> 5] = acc;
    __syncthreads();
    if (tid < 8) {
        float a = wsum[tid];
#pragma unroll
        for (int off = 4; off >= 1; off >>= 1)
            a += __shfl_xor_sync(0xffu, a, off);
        if (tid == 0) atomicAdd(out, a);
    }
}

// ---------------------------------------------------------------- launch
extern "C" void kernel_launch(void* const* d_in, const int* in_sizes, int n_in,
                              void* d_out, int out_size) {
    const float* emb = (const float*)d_in[0];
    const int*   seg = (const int*)d_in[1];
    float*       out = (float*)d_out;

    const int K1_SMEM = 12288 * 4 + 8 * 17 * 32 * 8;   // 83968 B
    static int attr_done = 0;
    if (!attr_done) {
        cudaFuncSetAttribute(k1_sums, cudaFuncAttributeMaxDynamicSharedMemorySize,
                             K1_SMEM);
        attr_done = 1;
    }

    k0_zero<<<8, 256>>>(out);

    dim3 g1(K1CH, B_), b1(32, 8);
    k1_sums<<<g1, b1, K1_SMEM>>>(emb, seg);

    k2_mid<<<1, 512>>>(out);

    dim3 g3(K3CH, B_);
    k3_var<<<g3, 256>>>(emb, seg, out);
}

// round 17
// speedup vs baseline: 1.2208x; 1.0032x over previous
#include <cuda_runtime.h>
#include <cstdint>

#define B_ 16
#define D_ 16
#define H_ 288
#define W_ 512
#define N_ (H_*W_)   // 147456
#define L_ 17
#define K1CH 18      // k1 chunks -> 8192 px/block; 288 blocks = ONE wave @2/SM
#define K3CH 24      // k3 chunks -> 6144 px/block; 384 blocks = ONE wave @3/SM

// persistent scratch. Zero at module load; k2 re-zeroes g_sums/g_cnt after
// consuming them, so every graph replay starts from a clean state.
__device__ float g_sums[B_][L_][D_];
__device__ float g_cnt[B_][L_];
__device__ float g_means[B_][L_][D_];
__device__ float g_w[B_][L_];

__device__ __forceinline__ uint32_t smem_u32(const void* p) {
    uint32_t a;
    asm("{ .reg .u64 t; cvta.to.shared.u64 t, %1; cvt.u32.u64 %0, t; }"
        : "=r"(a) : "l"(p));
    return a;
}

// ---------------------------------------------------------------- kernel 1
// Per-label sums + counts. cp.async per-warp 2-stage ring feeding TWO
// independent float2-packed accumulator arrays (pixels x,z -> chain A;
// y,w -> chain B). The chains provably never alias -> ptxas interleaves
// two 4-deep LDS->FADD->STS chains instead of one 8-deep chain.
// Lane-major layout: lane l always banks (2l,2l+1), label-independent.
__global__ void __launch_bounds__(256, 2) k1_sums(const float* __restrict__ emb,
                                                  const int* __restrict__ seg) {
    extern __shared__ float smf[];
    // layout: ring sd[2][8][2][256] floats (8192), then two float2 acc arrays
    float*  __restrict__ sd  = smf;                        // 32768 B
    float2* __restrict__ acA = (float2*)(smf + 8192);      // [8][17][32] f2
    float2* __restrict__ acB = acA + 8 * 17 * 32;          // [8][17][32] f2

    const int b    = blockIdx.y;
    const int lane = threadIdx.x;
    const int w    = threadIdx.y;
    const int chunk = N_ / K1CH;                   // 8192
    const int lo    = blockIdx.x * chunk;
    const int ITERS = chunk / 256;                 // 32 (256 px per warp-iter)

    float2* __restrict__ apA = acA + (w * 17) * 32 + lane;   // thread-private
    float2* __restrict__ apB = acB + (w * 17) * 32 + lane;
#pragma unroll
    for (int s = 0; s < L_; s++) {
        apA[s * 32] = make_float2(0.f, 0.f);
        apB[s * 32] = make_float2(0.f, 0.f);
    }

    const float* __restrict__ e0 = emb + ((size_t)b * D_ + 2 * w) * N_;
    const float* __restrict__ e1 = e0 + N_;
    const int*   __restrict__ sp = seg + (size_t)b * N_;

    // per-thread smem addresses: sd[buf][w][d][grp*128 + lane*4]
    const uint32_t sd0 = smem_u32(sd + w * 512 + lane * 4);
#define SD_DST(BUF, DD, GRP) (sd0 + (uint32_t)(((BUF)*4096 + (DD)*256 + (GRP)*128) * 4))

#define CPA16(DST, SRC)                                                        \
    asm volatile("cp.async.cg.shared.global [%0], [%1], 16;"                   \
                 :: "r"(DST), "l"((const void*)(SRC)) : "memory")

#define ISSUE(J)                                                               \
    {                                                                          \
        int _j = (J);                                                          \
        int _buf = _j & 1;                                                     \
        int _n = lo + _j * 256 + lane * 4;                                     \
        CPA16(SD_DST(_buf, 0, 0), e0 + _n);                                    \
        CPA16(SD_DST(_buf, 0, 1), e0 + _n + 128);                              \
        CPA16(SD_DST(_buf, 1, 0), e1 + _n);                                    \
        CPA16(SD_DST(_buf, 1, 1), e1 + _n + 128);                              \
        asm volatile("cp.async.commit_group;" ::: "memory");                   \
    }

    ISSUE(0); ISSUE(1);

    int cnt[16];
#pragma unroll
    for (int l = 0; l < 16; l++) cnt[l] = 0;

    // seg depth-1 register prefetch
    int n0 = lo + lane * 4;
    int4 sAx = *(const int4*)(sp + n0);
    int4 sAy = *(const int4*)(sp + n0 + 128);

    for (int it = 0; it < ITERS; ++it) {
        // prefetch next stage's seg
        int nn = (it + 1 < ITERS) ? (lo + (it + 1) * 256 + lane * 4) : n0;
        int4 sBx = *(const int4*)(sp + nn);
        int4 sBy = *(const int4*)(sp + nn + 128);

        // stage it must be complete (last iter: nothing may remain in flight)
        if (it == ITERS - 1) {
            asm volatile("cp.async.wait_group 0;" ::: "memory");
        } else {
            asm volatile("cp.async.wait_group 1;" ::: "memory");
        }

        const int buf = it & 1;
        const float* st = sd + buf * 4096 + w * 512;
        float4 v00 = *(const float4*)(st + lane * 4);            // dim0 grp0
        float4 v01 = *(const float4*)(st + 128 + lane * 4);      // dim0 grp1
        float4 v10 = *(const float4*)(st + 256 + lane * 4);      // dim1 grp0
        float4 v11 = *(const float4*)(st + 384 + lane * 4);      // dim1 grp1

        // two independent 4-deep RMW chains (A: x,z px; B: y,w px)
        { float2 t = apA[sAx.x * 32]; t.x += v00.x; t.y += v10.x; apA[sAx.x * 32] = t; }
        { float2 t = apB[sAx.y * 32]; t.x += v00.y; t.y += v10.y; apB[sAx.y * 32] = t; }
        { float2 t = apA[sAx.z * 32]; t.x += v00.z; t.y += v10.z; apA[sAx.z * 32] = t; }
        { float2 t = apB[sAx.w * 32]; t.x += v00.w; t.y += v10.w; apB[sAx.w * 32] = t; }
        { float2 t = apA[sAy.x * 32]; t.x += v01.x; t.y += v11.x; apA[sAy.x * 32] = t; }
        { float2 t = apB[sAy.y * 32]; t.x += v01.y; t.y += v11.y; apB[sAy.y * 32] = t; }
        { float2 t = apA[sAy.z * 32]; t.x += v01.z; t.y += v11.z; apA[sAy.z * 32] = t; }
        { float2 t = apB[sAy.w * 32]; t.x += v01.w; t.y += v11.w; apB[sAy.w * 32] = t; }

        // rotating count warp: every iteration counted exactly once
        if (((it - w) & 7) == 0) {
#pragma unroll
            for (int l = 1; l <= 16; l++)
                cnt[l-1] += (sAx.x == l) + (sAx.y == l) + (sAx.z == l) + (sAx.w == l)
                          + (sAy.x == l) + (sAy.y == l) + (sAy.z == l) + (sAy.w == l);
        }

        // refill ring: buffer it&1 fully consumed above (program order
        // guarantees the stage LDS completed before cp.async reissues)
        if (it + 2 < ITERS) ISSUE(it + 2);

        sAx = sBx; sAy = sBy;
    }
#undef ISSUE
#undef CPA16
#undef SD_DST

    // merge chains, reduce across the warp, commit via atomics
#pragma unroll
    for (int s = 1; s < L_; s++) {
        float2 ta = apA[s * 32];
        float2 tb = apB[s * 32];
        float v0 = ta.x + tb.x;
        float v1 = ta.y + tb.y;
#pragma unroll
        for (int off = 16; off >= 1; off >>= 1) {
            v0 += __shfl_xor_sync(0xffffffffu, v0, off);
            v1 += __shfl_xor_sync(0xffffffffu, v1, off);
        }
        if (lane == 0) {
            atomicAdd(&g_sums[b][s][2 * w],     v0);
            atomicAdd(&g_sums[b][s][2 * w + 1], v1);
        }
    }
#pragma unroll
    for (int l = 0; l < 16; l++) {
        int c = cnt[l];
#pragma unroll
        for (int off = 16; off >= 1; off >>= 1)
            c += __shfl_xor_sync(0xffffffffu, c, off);
        if (lane == 0 && c > 0) atomicAdd(&g_cnt[b][l+1], (float)c);
    }
}

// ---------------------------------------------------------------- kernel 2
// Finalize means/weights + pairwise push term; WRITES out[0] (k3 adds).
// Also re-zeroes g_sums/g_cnt after consuming them (replaces k0).
__global__ void k2_mid(float* out) {
    __shared__ int   pres[B_][L_];
    __shared__ float nlsh[B_];
    __shared__ float red[512];
    const int tid = threadIdx.x;

    for (int idx = tid; idx < B_*L_; idx += 512) {
        int b = idx / L_, l = idx % L_;
        pres[b][l] = (l != 0 && g_cnt[b][l] > 0.f) ? 1 : 0;
    }
    __syncthreads();
    if (tid < B_) {
        int nl = 0;
        for (int l = 0; l < L_; l++) nl += pres[tid][l];
        nlsh[tid] = (float)nl;
    }
    __syncthreads();

    for (int idx = tid; idx < B_*L_*D_; idx += 512) {
        int b = idx / (L_*D_);
        int l = (idx / D_) % L_;
        int d = idx % D_;
        float c = fmaxf(g_cnt[b][l], 1.f);
        g_means[b][l][d] = g_sums[b][l][d] / c;
    }
    for (int idx = tid; idx < B_*L_; idx += 512) {
        int b = idx / L_, l = idx % L_;
        float c  = fmaxf(g_cnt[b][l], 1.f);
        float nl = fmaxf(nlsh[b], 1.f);
        g_w[b][l] = pres[b][l] ? (1.f / (c * nl * (float)B_)) : 0.f;
    }
    __syncthreads();   // all reads of g_sums/g_cnt complete

    // re-zero accumulation scratch for the next graph replay
    for (int idx = tid; idx < B_*L_*D_; idx += 512)
        (&g_sums[0][0][0])[idx] = 0.f;
    for (int idx = tid; idx < B_*L_; idx += 512)
        (&g_cnt[0][0])[idx] = 0.f;

    float acc = 0.f;
    for (int idx = tid; idx < B_*L_*L_; idx += 512) {
        int b = idx / (L_*L_);
        int i = (idx / L_) % L_;
        int j = idx % L_;
        if (i != j && pres[b][i] && pres[b][j]) {
            float nl = nlsh[b];
            if (nl > 1.f) {
                float ss = 0.f;
#pragma unroll
                for (int d = 0; d < D_; d++) {
                    float dm = g_means[b][i][d] - g_means[b][j][d];
                    ss = fmaf(dm, dm, ss);
                }
                float dist = sqrtf(ss);
                float p = fmaxf(1.5f - dist, 0.f);
                float denom = fmaxf(nl * (nl - 1.f), 1.f);
                acc += (p * p) / denom * 0.5f / (float)B_;
            }
        }
    }
    red[tid] = acc;
    __syncthreads();
    for (int s = 256; s > 0; s >>= 1) {
        if (tid < s) red[tid] += red[tid + s];
        __syncthreads();
    }
    if (tid == 0) out[0] = red[0];     // overwrite: k3 atomicAdds on top
}

// ---------------------------------------------------------------- kernel 3
// Variance (pull) term, pre-weighted so it sums directly into the loss.
// 256 threads, 6 iters of 4 px, grid (24,16)=384 -> ONE wave @3/SM.
__global__ void __launch_bounds__(256, 3) k3_var(const float* __restrict__ emb,
                                                 const int* __restrict__ seg,
                                                 float* out) {
    const int b = blockIdx.y;
    __shared__ float sm_m[D_][L_];   // [d][l]: 17-float stride, conflict-free
    __shared__ float sm_w[L_];
    __shared__ float wsum[8];
    const int tid = threadIdx.x;

    for (int idx = tid; idx < D_*L_; idx += 256) {
        int d = idx / L_, l = idx % L_;
        sm_m[d][l] = g_means[b][l][d];
    }
    if (tid < L_) sm_w[tid] = g_w[b][tid];
    if (tid < 8) wsum[tid] = 0.f;
    __syncthreads();

    const int chunk = N_ / K3CH;     // 6144 = 6 * 256 * 4
    const int lo    = blockIdx.x * chunk;
    const float* __restrict__ e  = emb + (size_t)b * D_ * N_;
    const int* __restrict__   sp = seg + (size_t)b * N_;

    float acc = 0.f;
#pragma unroll
    for (int itr = 0; itr < 6; itr++) {
        int n = lo + itr * (256 * 4) + tid * 4;
        int4 s4 = *(const int4*)(sp + n);
        float ssx = 0.f, ssy = 0.f, ssz = 0.f, ssw = 0.f;

#pragma unroll
        for (int ph = 0; ph < 2; ph++) {
            float4 v[8];
#pragma unroll
            for (int d = 0; d < 8; d++)
                v[d] = *(const float4*)(e + (size_t)(ph * 8 + d) * N_ + n);
#pragma unroll
            for (int d = 0; d < 8; d++) {
                const float* mrow = &sm_m[ph * 8 + d][0];
                float dx = v[d].x - mrow[s4.x]; ssx = fmaf(dx, dx, ssx);
                float dy = v[d].y - mrow[s4.y]; ssy = fmaf(dy, dy, ssy);
                float dz = v[d].z - mrow[s4.z]; ssz = fmaf(dz, dz, ssz);
                float dw = v[d].w - mrow[s4.w]; ssw = fmaf(dw, dw, ssw);
            }
        }

#define FIN(SS, S)                                                             \
        {                                                                      \
            float nrm = sqrtf(fmaxf((SS), 1e-12f));                            \
            float t = fmaxf(nrm - 0.5f, 0.f);                                  \
            acc = fmaf(sm_w[S], t * t, acc);                                   \
        }
        FIN(ssx, s4.x); FIN(ssy, s4.y); FIN(ssz, s4.z); FIN(ssw, s4.w);
#undef FIN
    }
#pragma unroll
    for (int off = 16; off >= 1; off >>= 1)
        acc += __shfl_xor_sync(0xffffffffu, acc, off);
    if ((tid & 31) == 0) wsum[tid >> 5] = acc;
    __syncthreads();
    if (tid < 8) {
        float a = wsum[tid];
#pragma unroll
        for (int off = 4; off >= 1; off >>= 1)
            a += __shfl_xor_sync(0xffu, a, off);
        if (tid == 0) atomicAdd(out, a);
    }
}

// ---------------------------------------------------------------- launch
extern "C" void kernel_launch(void* const* d_in, const int* in_sizes, int n_in,
                              void* d_out, int out_size) {
    const float* emb = (const float*)d_in[0];
    const int*   seg = (const int*)d_in[1];
    float*       out = (float*)d_out;

    const int K1_SMEM = 8192 * 4 + 2 * (8 * 17 * 32) * 8;   // 102400 B
    static int attr_done = 0;
    if (!attr_done) {
        cudaFuncSetAttribute(k1_sums, cudaFuncAttributeMaxDynamicSharedMemorySize,
                             K1_SMEM);
        attr_done = 1;
    }

    dim3 g1(K1CH, B_), b1(32, 8);
    k1_sums<<<g1, b1, K1_SMEM>>>(emb, seg);

    k2_mid<<<1, 512>>>(out);

    dim3 g3(K3CH, B_);
    k3_var<<<g3, 256>>>(emb, seg, out);
}